// round 6
// baseline (speedup 1.0000x reference)
#include <cuda_runtime.h>
#include <math.h>
#include <stdint.h>

#define T_SEQ 2048
#define HDIM  2048
#define NH    32
#define NKVH  8
#define HD    64
#define NTOK  4096
#define KVDIM (NKVH*HD)

// ---------------- GEMM tile params ----------------
#define BM 128
#define BN 256
#define BK 32
#define PA 36
#define PBT 36
#define AS_U32 (BM*PA)          // 4608
#define BS_U32 (BN*PBT)         // 9216
#define STAGE_U32 (AS_U32 + BS_U32)   // 13824
#define GEMM_SMEM (3*STAGE_U32*4)     // 165888

// ---------------- flash params ----------------
#define FQ 128
#define FK 64
#define QP 68
#define VP 72
#define FLASH_SMEM ((FQ*QP + FK*QP + FQ*QP + FK*VP)*4)

// ---------------- scratch (tf32 bit domain; weights transposed [N][K]) ----------------
__device__ uint32_t g_x [NTOK * HDIM];
__device__ uint32_t g_wq[HDIM * HDIM];
__device__ uint32_t g_wk[KVDIM * HDIM];
__device__ uint32_t g_wv[KVDIM * HDIM];
__device__ uint32_t g_wo[HDIM * HDIM];
__device__ uint32_t g_q [NTOK * HDIM];
__device__ uint32_t g_k [NTOK * KVDIM];
__device__ uint32_t g_v [NTOK * KVDIM];
__device__ uint32_t g_attn[NTOK * HDIM];
__device__ float2   g_cs[T_SEQ * 32];

// ---------------- helpers ----------------
__device__ __forceinline__ uint32_t f2tf(float f) {
    uint32_t r;
    asm("cvt.rna.tf32.f32 %0, %1;" : "=r"(r) : "f"(f));
    return r;
}
__device__ __forceinline__ uint4 cvt4(float4 v) {
    uint4 u;
    u.x = f2tf(v.x); u.y = f2tf(v.y); u.z = f2tf(v.z); u.w = f2tf(v.w);
    return u;
}
__device__ __forceinline__ void cp16(uint32_t* s, const uint32_t* g) {
    uint32_t sa = (uint32_t)__cvta_generic_to_shared(s);
    asm volatile("cp.async.cg.shared.global [%0], [%1], 16;" :: "r"(sa), "l"(g));
}
__device__ __forceinline__ void cp_commit() { asm volatile("cp.async.commit_group;"); }
__device__ __forceinline__ void cp_wait1()  { asm volatile("cp.async.wait_group 1;"); }
__device__ __forceinline__ void mma_tf32(float* c, const uint32_t* a, uint32_t b0, uint32_t b1) {
    asm volatile(
        "mma.sync.aligned.m16n8k8.row.col.f32.tf32.tf32.f32 "
        "{%0,%1,%2,%3}, {%4,%5,%6,%7}, {%8,%9}, {%0,%1,%2,%3};"
        : "+f"(c[0]), "+f"(c[1]), "+f"(c[2]), "+f"(c[3])
        : "r"(a[0]), "r"(a[1]), "r"(a[2]), "r"(a[3]), "r"(b0), "r"(b1));
}
__device__ __forceinline__ void ldm4(uint32_t* r, const uint32_t* p) {
    uint32_t sa = (uint32_t)__cvta_generic_to_shared(p);
    asm volatile("ldmatrix.sync.aligned.m8n8.x4.shared.b16 {%0,%1,%2,%3}, [%4];"
                 : "=r"(r[0]), "=r"(r[1]), "=r"(r[2]), "=r"(r[3]) : "r"(sa));
}

// ---------------- fp32 -> tf32 bits bulk convert ----------------
__global__ void cvt_tf32_kernel(const float4* __restrict__ src, uint4* __restrict__ dst, int n4) {
    int i = blockIdx.x * blockDim.x + threadIdx.x;
    if (i < n4) dst[i] = cvt4(src[i]);
}

// ---------------- fp32 [K][N] -> tf32 bits transposed [N][K] ----------------
__global__ void cvt_t_kernel(const float* __restrict__ src, uint32_t* __restrict__ dst,
                             int N, int K) {
    __shared__ float tile[32][33];
    int n0 = blockIdx.x * 32, k0 = blockIdx.y * 32;
    int tx = threadIdx.x & 31, ty = threadIdx.x >> 5;   // 32 x 8
#pragma unroll
    for (int r = 0; r < 4; r++)
        tile[ty + 8 * r][tx] = src[(size_t)(k0 + ty + 8 * r) * N + n0 + tx];
    __syncthreads();
#pragma unroll
    for (int r = 0; r < 4; r++)
        dst[(size_t)(n0 + ty + 8 * r) * K + k0 + tx] = f2tf(tile[tx][ty + 8 * r]);
}

// ---------------- cos/sin ----------------
__global__ void cossin_kernel(float2* __restrict__ cs) {
    int idx = blockIdx.x * blockDim.x + threadIdx.x;
    int t = idx >> 5;
    int i = idx & 31;
    const double r = 0.74989420933245582;   // 10000^(-1/32)
    double inv = 1.0;
    for (int j = 0; j < i; j++) inv *= r;
    double f = (double)t * inv;
    double kq = rint(f * 0.15915494309189535);
    double rem = f - kq * 6.283185307179586476925287;
    float fr = (float)rem;
    cs[idx] = make_float2(cosf(fr), sinf(fr));
}

// ---------------- GEMM mainloop: A row-major [M][K], Bt K-major [N][K] ----------------
struct GemmCore {
    float acc[4][8][4];
    const uint32_t* A; const uint32_t* Bt;
    int K, brow, bcol, tid, lane, w, wm, wn;
    uint32_t* sm;

    __device__ __forceinline__ void load_stage(int s, int k0) {
        uint32_t* As = sm + s * STAGE_U32;
        uint32_t* Bs = As + AS_U32;
        const int kq = (tid & 7) * 4;
        const int mbase = tid >> 3;        // 0..31
#pragma unroll
        for (int r = 0; r < 4; r++) {
            int m = mbase + 32 * r;
            cp16(&As[m * PA + kq], A + (size_t)(brow + m) * K + k0 + kq);
        }
#pragma unroll
        for (int r = 0; r < 8; r++) {
            int n = mbase + 32 * r;
            cp16(&Bs[n * PBT + kq], Bt + (size_t)(bcol + n) * K + k0 + kq);
        }
    }

    __device__ __forceinline__ void run() {
#pragma unroll
        for (int mt = 0; mt < 4; mt++)
#pragma unroll
            for (int nt = 0; nt < 8; nt++)
#pragma unroll
                for (int i = 0; i < 4; i++) acc[mt][nt][i] = 0.f;

        const int ntk = K / BK;
        load_stage(0, 0);   cp_commit();
        load_stage(1, BK);  cp_commit();

        const int aRow    = lane & 15;
        const int aColSel = (lane >> 4) * 4;
        const int bj      = lane >> 3;     // 0..3
        const int br      = lane & 7;

        int cur = 0;
        for (int t = 0; t < ntk; t++) {
            cp_wait1();
            __syncthreads();
            {
                int pre = cur + 2 >= 3 ? cur - 1 : cur + 2;
                if (t + 2 < ntk) load_stage(pre, (t + 2) * BK);
                cp_commit();
            }
            uint32_t* As = sm + cur * STAGE_U32;
            uint32_t* Bs = As + AS_U32;
#pragma unroll
            for (int ks = 0; ks < 4; ks++) {
                uint32_t a[4][4];
#pragma unroll
                for (int mt = 0; mt < 4; mt++)
                    ldm4(a[mt], &As[(wm * 64 + mt * 16 + aRow) * PA + ks * 8 + aColSel]);
#pragma unroll
                for (int p = 0; p < 4; p++) {
                    uint32_t bfr[4];
                    ldm4(bfr, &Bs[(wn * 64 + (2 * p + (bj >> 1)) * 8 + br) * PBT
                                  + ks * 8 + (bj & 1) * 4]);
#pragma unroll
                    for (int mt = 0; mt < 4; mt++) {
                        mma_tf32(acc[mt][2 * p],     a[mt], bfr[0], bfr[1]);
                        mma_tf32(acc[mt][2 * p + 1], a[mt], bfr[2], bfr[3]);
                    }
                }
            }
            cur = (cur + 1 == 3) ? 0 : cur + 1;
        }
    }
};

// ---------------- fused QKV GEMM with RoPE epilogue, tf32-bits out ----------------
__global__ __launch_bounds__(256, 1) void gemm_qkv(
    const uint32_t* __restrict__ A,
    const uint32_t* __restrict__ wq, const uint32_t* __restrict__ wk, const uint32_t* __restrict__ wv,
    uint32_t* __restrict__ q, uint32_t* __restrict__ k, uint32_t* __restrict__ v,
    const float2* __restrict__ cs)
{
    extern __shared__ uint32_t smu[];
    const int bx = blockIdx.x;
    int bcol, N;
    const uint32_t* B; uint32_t* C; bool rope; float scale;
    if (bx < 8)       { bcol = bx * BN;        N = HDIM;  B = wq; C = q; rope = true;  scale = 0.125f; }
    else if (bx < 10) { bcol = (bx - 8) * BN;  N = KVDIM; B = wk; C = k; rope = true;  scale = 1.f; }
    else              { bcol = (bx - 10) * BN; N = KVDIM; B = wv; C = v; rope = false; scale = 1.f; }

    GemmCore gc;
    gc.A = A; gc.Bt = B; gc.K = HDIM;
    gc.brow = blockIdx.y * BM; gc.bcol = bcol;
    gc.tid = threadIdx.x; gc.lane = gc.tid & 31; gc.w = gc.tid >> 5;
    gc.wm = gc.w >> 2; gc.wn = gc.w & 3; gc.sm = smu;
    gc.run();

    const int tig = gc.lane & 3;
    const int g   = gc.lane >> 2;
#pragma unroll
    for (int mt = 0; mt < 4; mt++) {
        int row0 = gc.brow + gc.wm * 64 + mt * 16 + g;
#pragma unroll
        for (int nt = 0; nt < 8; nt++) {
            int col = bcol + gc.wn * 64 + nt * 8 + 2 * tig;
#pragma unroll
            for (int hh = 0; hh < 2; hh++) {
                int row = row0 + hh * 8;
                float re = gc.acc[mt][nt][2 * hh + 0];
                float im = gc.acc[mt][nt][2 * hh + 1];
                if (rope) {
                    int t_ = row & (T_SEQ - 1);
                    int i_ = (col & 63) >> 1;
                    float2 c = cs[(t_ << 5) + i_];
                    float nre = re * c.x - im * c.y;
                    float nim = re * c.y + im * c.x;
                    re = nre; im = nim;
                }
                re *= scale; im *= scale;
                uint2 u = make_uint2(f2tf(re), f2tf(im));
                *(uint2*)&C[(size_t)row * N + col] = u;
            }
        }
    }
}

// ---------------- output projection GEMM: u32 in, fp32 out ----------------
__global__ __launch_bounds__(256, 1) void gemm_wo(
    const uint32_t* __restrict__ A, const uint32_t* __restrict__ B,
    float* __restrict__ C)
{
    extern __shared__ uint32_t smu[];
    GemmCore gc;
    gc.A = A; gc.Bt = B; gc.K = HDIM;
    gc.brow = blockIdx.y * BM; gc.bcol = blockIdx.x * BN;
    gc.tid = threadIdx.x; gc.lane = gc.tid & 31; gc.w = gc.tid >> 5;
    gc.wm = gc.w >> 2; gc.wn = gc.w & 3; gc.sm = smu;
    gc.run();

    const int tig = gc.lane & 3;
    const int g   = gc.lane >> 2;
#pragma unroll
    for (int mt = 0; mt < 4; mt++) {
        int row = gc.brow + gc.wm * 64 + mt * 16 + g;
#pragma unroll
        for (int nt = 0; nt < 8; nt++) {
            int col = gc.bcol + gc.wn * 64 + nt * 8 + 2 * tig;
            *(float2*)&C[(size_t)row * HDIM + col]       = make_float2(gc.acc[mt][nt][0], gc.acc[mt][nt][1]);
            *(float2*)&C[(size_t)(row + 8) * HDIM + col] = make_float2(gc.acc[mt][nt][2], gc.acc[mt][nt][3]);
        }
    }
}

// ---------------- tensor-core causal flash attention (all tf32 bits) ----------------
__global__ __launch_bounds__(256, 2) void flash_tc(
    const uint32_t* __restrict__ Q, const uint32_t* __restrict__ K,
    const uint32_t* __restrict__ V, uint32_t* __restrict__ O)
{
    extern __shared__ uint32_t smu[];
    uint32_t* Qs = smu;                          // [128][QP]
    uint32_t* Ks = smu + FQ * QP;                // [64][QP]   K-major [j][d]
    uint32_t* Ps = smu + FQ * QP + FK * QP;      // [128][QP]
    uint32_t* Vs = smu + 2 * FQ * QP + FK * QP;  // [64][VP]   [j][d]

    const int tid  = threadIdx.x;
    const int lane = tid & 31;
    const int w    = tid >> 5;
    const int g    = lane >> 2;
    const int tig  = lane & 3;
    const int qlRow = lane & 15;
    const int qlCol = (lane >> 4) * 4;
    const int bj    = lane >> 3;
    const int br    = lane & 7;

    const int qtile = blockIdx.x;
    const int h     = blockIdx.y;
    const int b     = blockIdx.z;
    const int kvh   = h >> 2;
    const size_t qtok0 = (size_t)b * T_SEQ + qtile * FQ;

    {
        const int row = tid >> 4;
        const int c4  = tid & 15;
#pragma unroll
        for (int r = 0; r < 8; r++) {
            int rr = row + r * 16;
            *(uint4*)&Qs[rr * QP + c4 * 4] =
                *(const uint4*)(Q + (qtok0 + rr) * HDIM + h * HD + c4 * 4);
        }
    }

    float m[2], l[2], oacc[8][4];
    m[0] = m[1] = -1e30f; l[0] = l[1] = 0.f;
#pragma unroll
    for (int nt = 0; nt < 8; nt++)
#pragma unroll
        for (int i = 0; i < 4; i++) oacc[nt][i] = 0.f;

    const int ktmax = 2 * qtile + 1;

    for (int kt = 0; kt <= ktmax; kt++) {
        const size_t ktok0 = (size_t)b * T_SEQ + kt * FK;
        __syncthreads();
        {
            const int row = tid >> 4;
            const int c4  = tid & 15;
#pragma unroll
            for (int r = 0; r < 4; r++) {
                int rr = row + r * 16;
                *(uint4*)&Ks[rr * QP + c4 * 4] =
                    *(const uint4*)(K + (ktok0 + rr) * KVDIM + kvh * HD + c4 * 4);
                *(uint4*)&Vs[rr * VP + c4 * 4] =
                    *(const uint4*)(V + (ktok0 + rr) * KVDIM + kvh * HD + c4 * 4);
            }
        }
        __syncthreads();

        float sacc[8][4];
#pragma unroll
        for (int nt = 0; nt < 8; nt++)
#pragma unroll
            for (int i = 0; i < 4; i++) sacc[nt][i] = 0.f;

#pragma unroll
        for (int ks = 0; ks < 8; ks++) {
            uint32_t af[4];
            ldm4(af, &Qs[(w * 16 + qlRow) * QP + ks * 8 + qlCol]);
#pragma unroll
            for (int p = 0; p < 4; p++) {
                uint32_t bfr[4];
                ldm4(bfr, &Ks[((2 * p + (bj >> 1)) * 8 + br) * QP + ks * 8 + (bj & 1) * 4]);
                mma_tf32(sacc[2 * p],     af, bfr[0], bfr[1]);
                mma_tf32(sacc[2 * p + 1], af, bfr[2], bfr[3]);
            }
        }

        if (kt >= 2 * qtile) {
#pragma unroll
            for (int nt = 0; nt < 8; nt++)
#pragma unroll
                for (int i = 0; i < 4; i++) {
                    int rowg = qtile * FQ + w * 16 + g + (i >> 1) * 8;
                    int colg = kt * FK + nt * 8 + 2 * tig + (i & 1);
                    if (colg > rowg) sacc[nt][i] = -1e30f;
                }
        }

#pragma unroll
        for (int hh = 0; hh < 2; hh++) {
            float mx = -1e30f;
#pragma unroll
            for (int nt = 0; nt < 8; nt++)
                mx = fmaxf(mx, fmaxf(sacc[nt][2 * hh], sacc[nt][2 * hh + 1]));
            mx = fmaxf(mx, __shfl_xor_sync(0xffffffffu, mx, 1));
            mx = fmaxf(mx, __shfl_xor_sync(0xffffffffu, mx, 2));
            float mn = fmaxf(m[hh], mx);
            float fac = __expf(m[hh] - mn);
            m[hh] = mn;
            float rs = 0.f;
#pragma unroll
            for (int nt = 0; nt < 8; nt++) {
                float p0 = __expf(sacc[nt][2 * hh]     - mn);
                float p1 = __expf(sacc[nt][2 * hh + 1] - mn);
                sacc[nt][2 * hh] = p0; sacc[nt][2 * hh + 1] = p1;
                rs += p0 + p1;
            }
            rs += __shfl_xor_sync(0xffffffffu, rs, 1);
            rs += __shfl_xor_sync(0xffffffffu, rs, 2);
            l[hh] = l[hh] * fac + rs;
#pragma unroll
            for (int nt = 0; nt < 8; nt++) {
                oacc[nt][2 * hh]     *= fac;
                oacc[nt][2 * hh + 1] *= fac;
            }
        }

#pragma unroll
        for (int nt = 0; nt < 8; nt++) {
            uint2 p01, p23;
            p01.x = f2tf(sacc[nt][0]); p01.y = f2tf(sacc[nt][1]);
            p23.x = f2tf(sacc[nt][2]); p23.y = f2tf(sacc[nt][3]);
            *(uint2*)&Ps[(w * 16 + g)     * QP + nt * 8 + 2 * tig] = p01;
            *(uint2*)&Ps[(w * 16 + g + 8) * QP + nt * 8 + 2 * tig] = p23;
        }
        __syncwarp();

#pragma unroll
        for (int ks = 0; ks < 8; ks++) {
            uint32_t pf[4];
            ldm4(pf, &Ps[(w * 16 + qlRow) * QP + ks * 8 + qlCol]);
#pragma unroll
            for (int nt = 0; nt < 8; nt++) {
                uint32_t b0 = Vs[(ks * 8 + tig) * VP + nt * 8 + g];
                uint32_t b1 = Vs[(ks * 8 + tig + 4) * VP + nt * 8 + g];
                mma_tf32(oacc[nt], pf, b0, b1);
            }
        }
    }

    float inv0 = 1.0f / l[0], inv1 = 1.0f / l[1];
#pragma unroll
    for (int nt = 0; nt < 8; nt++) {
        size_t row0 = qtok0 + w * 16 + g;
        int col = h * HD + nt * 8 + 2 * tig;
        uint2 u0 = make_uint2(f2tf(oacc[nt][0] * inv0), f2tf(oacc[nt][1] * inv0));
        uint2 u1 = make_uint2(f2tf(oacc[nt][2] * inv1), f2tf(oacc[nt][3] * inv1));
        *(uint2*)&O[row0 * HDIM + col]       = u0;
        *(uint2*)&O[(row0 + 8) * HDIM + col] = u1;
    }
}

// ---------------- launch ----------------
extern "C" void kernel_launch(void* const* d_in, const int* in_sizes, int n_in,
                              void* d_out, int out_size) {
    const float* x  = (const float*)d_in[0];
    const float* wq = (const float*)d_in[1];
    const float* wk = (const float*)d_in[2];
    const float* wv = (const float*)d_in[3];
    const float* wo = (const float*)d_in[4];
    float* out = (float*)d_out;

    uint32_t *xb, *wqb, *wkb, *wvb, *wob, *q, *k, *v, *attn;
    float2* cs;
    cudaGetSymbolAddress((void**)&xb,   g_x);
    cudaGetSymbolAddress((void**)&wqb,  g_wq);
    cudaGetSymbolAddress((void**)&wkb,  g_wk);
    cudaGetSymbolAddress((void**)&wvb,  g_wv);
    cudaGetSymbolAddress((void**)&wob,  g_wo);
    cudaGetSymbolAddress((void**)&q,    g_q);
    cudaGetSymbolAddress((void**)&k,    g_k);
    cudaGetSymbolAddress((void**)&v,    g_v);
    cudaGetSymbolAddress((void**)&attn, g_attn);
    cudaGetSymbolAddress((void**)&cs,   g_cs);

    cudaFuncSetAttribute(gemm_qkv, cudaFuncAttributeMaxDynamicSharedMemorySize, GEMM_SMEM);
    cudaFuncSetAttribute(gemm_wo,  cudaFuncAttributeMaxDynamicSharedMemorySize, GEMM_SMEM);
    cudaFuncSetAttribute(flash_tc, cudaFuncAttributeMaxDynamicSharedMemorySize, FLASH_SMEM);

    cossin_kernel<<<(T_SEQ * 32) / 256, 256>>>(cs);

    {
        int n4 = NTOK * HDIM / 4;
        cvt_tf32_kernel<<<(n4 + 255) / 256, 256>>>((const float4*)x, (uint4*)xb, n4);
    }
    cvt_t_kernel<<<dim3(HDIM / 32, HDIM / 32),  256>>>(wq, wqb, HDIM,  HDIM);
    cvt_t_kernel<<<dim3(KVDIM / 32, HDIM / 32), 256>>>(wk, wkb, KVDIM, HDIM);
    cvt_t_kernel<<<dim3(KVDIM / 32, HDIM / 32), 256>>>(wv, wvb, KVDIM, HDIM);
    cvt_t_kernel<<<dim3(HDIM / 32, HDIM / 32),  256>>>(wo, wob, HDIM,  HDIM);

    gemm_qkv<<<dim3(12, NTOK / BM), 256, GEMM_SMEM>>>(xb, wqb, wkb, wvb, q, k, v, cs);

    flash_tc<<<dim3(T_SEQ / FQ, NH, 2), 256, FLASH_SMEM>>>(q, k, v, attn);

    gemm_wo<<<dim3(HDIM / BN, NTOK / BM), 256, GEMM_SMEM>>>(attn, wob, out);
}

// round 8
// speedup vs baseline: 1.0523x; 1.0523x over previous
#include <cuda_runtime.h>
#include <math.h>
#include <stdint.h>

#define T_SEQ 2048
#define HDIM  2048
#define NH    32
#define NKVH  8
#define HD    64
#define NTOK  4096
#define KVDIM (NKVH*HD)

// ---------------- GEMM tile params (128x128, 2 CTAs/SM) ----------------
#define BM 128
#define BN 128
#define BK 32
#define PA 36
#define PBT 36
#define AS_U32 (BM*PA)                 // 4608
#define BS_U32 (BN*PBT)                // 4608
#define STAGE_U32 (AS_U32 + BS_U32)    // 9216
#define GEMM_SMEM (3*STAGE_U32*4)      // 110592

// ---------------- flash params ----------------
#define FQ 128
#define FK 64
#define QP 68
#define VP 72
#define FLASH_SMEM ((FQ*QP + FK*QP + FQ*QP + FK*VP)*4)

// ---------------- scratch (tf32 bit domain; weights transposed [N][K]) ----------------
__device__ uint32_t g_x [NTOK * HDIM];
__device__ uint32_t g_wq[HDIM * HDIM];
__device__ uint32_t g_wk[KVDIM * HDIM];
__device__ uint32_t g_wv[KVDIM * HDIM];
__device__ uint32_t g_wo[HDIM * HDIM];
__device__ uint32_t g_q [NTOK * HDIM];
__device__ uint32_t g_k [NTOK * KVDIM];
__device__ uint32_t g_v [NTOK * KVDIM];
__device__ uint32_t g_attn[NTOK * HDIM];
__device__ float2   g_cs[T_SEQ * 32];

// ---------------- helpers ----------------
__device__ __forceinline__ uint32_t f2tf(float f) {
    uint32_t r;
    asm("cvt.rna.tf32.f32 %0, %1;" : "=r"(r) : "f"(f));
    return r;
}
__device__ __forceinline__ uint4 cvt4(float4 v) {
    uint4 u;
    u.x = f2tf(v.x); u.y = f2tf(v.y); u.z = f2tf(v.z); u.w = f2tf(v.w);
    return u;
}
__device__ __forceinline__ void cp16(uint32_t* s, const uint32_t* g) {
    uint32_t sa = (uint32_t)__cvta_generic_to_shared(s);
    asm volatile("cp.async.cg.shared.global [%0], [%1], 16;" :: "r"(sa), "l"(g));
}
__device__ __forceinline__ void cp_commit() { asm volatile("cp.async.commit_group;"); }
__device__ __forceinline__ void cp_wait1()  { asm volatile("cp.async.wait_group 1;"); }
__device__ __forceinline__ void mma_tf32(float* c, const uint32_t* a, uint32_t b0, uint32_t b1) {
    asm volatile(
        "mma.sync.aligned.m16n8k8.row.col.f32.tf32.tf32.f32 "
        "{%0,%1,%2,%3}, {%4,%5,%6,%7}, {%8,%9}, {%0,%1,%2,%3};"
        : "+f"(c[0]), "+f"(c[1]), "+f"(c[2]), "+f"(c[3])
        : "r"(a[0]), "r"(a[1]), "r"(a[2]), "r"(a[3]), "r"(b0), "r"(b1));
}
__device__ __forceinline__ void ldm4(uint32_t* r, const uint32_t* p) {
    uint32_t sa = (uint32_t)__cvta_generic_to_shared(p);
    asm volatile("ldmatrix.sync.aligned.m8n8.x4.shared.b16 {%0,%1,%2,%3}, [%4];"
                 : "=r"(r[0]), "=r"(r[1]), "=r"(r[2]), "=r"(r[3]) : "r"(sa));
}

// ---------------- fp32 -> tf32 bits bulk convert ----------------
__global__ void cvt_tf32_kernel(const float4* __restrict__ src, uint4* __restrict__ dst, int n4) {
    int i = blockIdx.x * blockDim.x + threadIdx.x;
    if (i < n4) dst[i] = cvt4(src[i]);
}

// ---------------- fp32 [K][N] -> tf32 bits transposed [N][K] ----------------
__global__ void cvt_t_kernel(const float* __restrict__ src, uint32_t* __restrict__ dst,
                             int N, int K) {
    __shared__ float tile[32][33];
    int n0 = blockIdx.x * 32, k0 = blockIdx.y * 32;
    int tx = threadIdx.x & 31, ty = threadIdx.x >> 5;   // 32 x 8
#pragma unroll
    for (int r = 0; r < 4; r++)
        tile[ty + 8 * r][tx] = src[(size_t)(k0 + ty + 8 * r) * N + n0 + tx];
    __syncthreads();
#pragma unroll
    for (int r = 0; r < 4; r++)
        dst[(size_t)(n0 + ty + 8 * r) * K + k0 + tx] = f2tf(tile[tx][ty + 8 * r]);
}

// ---------------- cos/sin ----------------
__global__ void cossin_kernel(float2* __restrict__ cs) {
    int idx = blockIdx.x * blockDim.x + threadIdx.x;
    int t = idx >> 5;
    int i = idx & 31;
    const double r = 0.74989420933245582;   // 10000^(-1/32)
    double inv = 1.0;
    for (int j = 0; j < i; j++) inv *= r;
    double f = (double)t * inv;
    double kq = rint(f * 0.15915494309189535);
    double rem = f - kq * 6.283185307179586476925287;
    float fr = (float)rem;
    cs[idx] = make_float2(cosf(fr), sinf(fr));
}

// ---------------- GEMM mainloop: A row-major [M][K], Bt K-major [N][K] ----------------
// 8 warps as 2(M) x 4(N); warp tile 64x32; acc 64 regs/thread.
struct GemmCore {
    float acc[4][4][4];
    const uint32_t* A; const uint32_t* Bt;
    int K, brow, bcol, tid, lane, w, wm, wn;
    uint32_t* sm;

    __device__ __forceinline__ void load_stage(int s, int k0) {
        uint32_t* As = sm + s * STAGE_U32;
        uint32_t* Bs = As + AS_U32;
        const int kq = (tid & 7) * 4;
        const int mbase = tid >> 3;        // 0..31
#pragma unroll
        for (int r = 0; r < 4; r++) {
            int m = mbase + 32 * r;
            cp16(&As[m * PA + kq], A + (size_t)(brow + m) * K + k0 + kq);
        }
#pragma unroll
        for (int r = 0; r < 4; r++) {
            int n = mbase + 32 * r;
            cp16(&Bs[n * PBT + kq], Bt + (size_t)(bcol + n) * K + k0 + kq);
        }
    }

    __device__ __forceinline__ void run() {
#pragma unroll
        for (int mt = 0; mt < 4; mt++)
#pragma unroll
            for (int nt = 0; nt < 4; nt++)
#pragma unroll
                for (int i = 0; i < 4; i++) acc[mt][nt][i] = 0.f;

        const int ntk = K / BK;
        load_stage(0, 0);   cp_commit();
        load_stage(1, BK);  cp_commit();

        const int aRow    = lane & 15;
        const int aColSel = (lane >> 4) * 4;
        const int bj      = lane >> 3;     // 0..3
        const int br      = lane & 7;

        int cur = 0;
        for (int t = 0; t < ntk; t++) {
            cp_wait1();
            __syncthreads();
            {
                int pre = cur + 2;
                if (pre >= 3) pre -= 3;
                if (t + 2 < ntk) load_stage(pre, (t + 2) * BK);
                cp_commit();
            }
            uint32_t* As = sm + cur * STAGE_U32;
            uint32_t* Bs = As + AS_U32;
#pragma unroll
            for (int ks = 0; ks < 4; ks++) {
                uint32_t a[4][4];
#pragma unroll
                for (int mt = 0; mt < 4; mt++)
                    ldm4(a[mt], &As[(wm * 64 + mt * 16 + aRow) * PA + ks * 8 + aColSel]);
#pragma unroll
                for (int p = 0; p < 2; p++) {
                    uint32_t bfr[4];
                    ldm4(bfr, &Bs[(wn * 32 + (2 * p + (bj >> 1)) * 8 + br) * PBT
                                  + ks * 8 + (bj & 1) * 4]);
#pragma unroll
                    for (int mt = 0; mt < 4; mt++) {
                        mma_tf32(acc[mt][2 * p],     a[mt], bfr[0], bfr[1]);
                        mma_tf32(acc[mt][2 * p + 1], a[mt], bfr[2], bfr[3]);
                    }
                }
            }
            cur = (cur + 1 == 3) ? 0 : cur + 1;
        }
    }
};

// ---------------- fused QKV GEMM with RoPE epilogue, tf32-bits out ----------------
// grid.x: 0..15 wq, 16..19 wk, 20..23 wv
__global__ __launch_bounds__(256, 2) void gemm_qkv(
    const uint32_t* __restrict__ A,
    const uint32_t* __restrict__ wq, const uint32_t* __restrict__ wk, const uint32_t* __restrict__ wv,
    uint32_t* __restrict__ q, uint32_t* __restrict__ k, uint32_t* __restrict__ v,
    const float2* __restrict__ cs)
{
    extern __shared__ uint32_t smu[];
    const int bx = blockIdx.x;
    int bcol, N;
    const uint32_t* B; uint32_t* C; bool rope; float scale;
    if (bx < 16)      { bcol = bx * BN;        N = HDIM;  B = wq; C = q; rope = true;  scale = 0.125f; }
    else if (bx < 20) { bcol = (bx - 16) * BN; N = KVDIM; B = wk; C = k; rope = true;  scale = 1.f; }
    else              { bcol = (bx - 20) * BN; N = KVDIM; B = wv; C = v; rope = false; scale = 1.f; }

    GemmCore gc;
    gc.A = A; gc.Bt = B; gc.K = HDIM;
    gc.brow = blockIdx.y * BM; gc.bcol = bcol;
    gc.tid = threadIdx.x; gc.lane = gc.tid & 31; gc.w = gc.tid >> 5;
    gc.wm = gc.w >> 2; gc.wn = gc.w & 3; gc.sm = smu;
    gc.run();

    const int tig = gc.lane & 3;
    const int g   = gc.lane >> 2;
#pragma unroll
    for (int mt = 0; mt < 4; mt++) {
        int row0 = gc.brow + gc.wm * 64 + mt * 16 + g;
#pragma unroll
        for (int nt = 0; nt < 4; nt++) {
            int col = bcol + gc.wn * 32 + nt * 8 + 2 * tig;
#pragma unroll
            for (int hh = 0; hh < 2; hh++) {
                int row = row0 + hh * 8;
                float re = gc.acc[mt][nt][2 * hh + 0];
                float im = gc.acc[mt][nt][2 * hh + 1];
                if (rope) {
                    int t_ = row & (T_SEQ - 1);
                    int i_ = (col & 63) >> 1;
                    float2 c = cs[(t_ << 5) + i_];
                    float nre = re * c.x - im * c.y;
                    float nim = re * c.y + im * c.x;
                    re = nre; im = nim;
                }
                re *= scale; im *= scale;
                uint2 u = make_uint2(f2tf(re), f2tf(im));
                *(uint2*)&C[(size_t)row * N + col] = u;
            }
        }
    }
}

// ---------------- output projection GEMM: u32 in, fp32 out ----------------
__global__ __launch_bounds__(256, 2) void gemm_wo(
    const uint32_t* __restrict__ A, const uint32_t* __restrict__ B,
    float* __restrict__ C)
{
    extern __shared__ uint32_t smu[];
    GemmCore gc;
    gc.A = A; gc.Bt = B; gc.K = HDIM;
    gc.brow = blockIdx.y * BM; gc.bcol = blockIdx.x * BN;
    gc.tid = threadIdx.x; gc.lane = gc.tid & 31; gc.w = gc.tid >> 5;
    gc.wm = gc.w >> 2; gc.wn = gc.w & 3; gc.sm = smu;
    gc.run();

    const int tig = gc.lane & 3;
    const int g   = gc.lane >> 2;
#pragma unroll
    for (int mt = 0; mt < 4; mt++) {
        int row = gc.brow + gc.wm * 64 + mt * 16 + g;
#pragma unroll
        for (int nt = 0; nt < 4; nt++) {
            int col = gc.bcol + gc.wn * 32 + nt * 8 + 2 * tig;
            *(float2*)&C[(size_t)row * HDIM + col]       = make_float2(gc.acc[mt][nt][0], gc.acc[mt][nt][1]);
            *(float2*)&C[(size_t)(row + 8) * HDIM + col] = make_float2(gc.acc[mt][nt][2], gc.acc[mt][nt][3]);
        }
    }
}

// ---------------- tensor-core causal flash attention (all tf32 bits) ----------------
__global__ __launch_bounds__(256, 2) void flash_tc(
    const uint32_t* __restrict__ Q, const uint32_t* __restrict__ K,
    const uint32_t* __restrict__ V, uint32_t* __restrict__ O)
{
    extern __shared__ uint32_t smu[];
    uint32_t* Qs = smu;                          // [128][QP]
    uint32_t* Ks = smu + FQ * QP;                // [64][QP]   K-major [j][d]
    uint32_t* Ps = smu + FQ * QP + FK * QP;      // [128][QP]
    uint32_t* Vs = smu + 2 * FQ * QP + FK * QP;  // [64][VP]   [j][d]

    const int tid  = threadIdx.x;
    const int lane = tid & 31;
    const int w    = tid >> 5;
    const int g    = lane >> 2;
    const int tig  = lane & 3;
    const int qlRow = lane & 15;
    const int qlCol = (lane >> 4) * 4;
    const int bj    = lane >> 3;
    const int br    = lane & 7;

    const int qtile = blockIdx.x;
    const int h     = blockIdx.y;
    const int b     = blockIdx.z;
    const int kvh   = h >> 2;
    const size_t qtok0 = (size_t)b * T_SEQ + qtile * FQ;

    {
        const int row = tid >> 4;
        const int c4  = tid & 15;
#pragma unroll
        for (int r = 0; r < 8; r++) {
            int rr = row + r * 16;
            *(uint4*)&Qs[rr * QP + c4 * 4] =
                *(const uint4*)(Q + (qtok0 + rr) * HDIM + h * HD + c4 * 4);
        }
    }

    float m[2], l[2], oacc[8][4];
    m[0] = m[1] = -1e30f; l[0] = l[1] = 0.f;
#pragma unroll
    for (int nt = 0; nt < 8; nt++)
#pragma unroll
        for (int i = 0; i < 4; i++) oacc[nt][i] = 0.f;

    const int ktmax = 2 * qtile + 1;

    for (int kt = 0; kt <= ktmax; kt++) {
        const size_t ktok0 = (size_t)b * T_SEQ + kt * FK;
        __syncthreads();
        {
            const int row = tid >> 4;
            const int c4  = tid & 15;
#pragma unroll
            for (int r = 0; r < 4; r++) {
                int rr = row + r * 16;
                *(uint4*)&Ks[rr * QP + c4 * 4] =
                    *(const uint4*)(K + (ktok0 + rr) * KVDIM + kvh * HD + c4 * 4);
                *(uint4*)&Vs[rr * VP + c4 * 4] =
                    *(const uint4*)(V + (ktok0 + rr) * KVDIM + kvh * HD + c4 * 4);
            }
        }
        __syncthreads();

        float sacc[8][4];
#pragma unroll
        for (int nt = 0; nt < 8; nt++)
#pragma unroll
            for (int i = 0; i < 4; i++) sacc[nt][i] = 0.f;

#pragma unroll
        for (int ks = 0; ks < 8; ks++) {
            uint32_t af[4];
            ldm4(af, &Qs[(w * 16 + qlRow) * QP + ks * 8 + qlCol]);
#pragma unroll
            for (int p = 0; p < 4; p++) {
                uint32_t bfr[4];
                ldm4(bfr, &Ks[((2 * p + (bj >> 1)) * 8 + br) * QP + ks * 8 + (bj & 1) * 4]);
                mma_tf32(sacc[2 * p],     af, bfr[0], bfr[1]);
                mma_tf32(sacc[2 * p + 1], af, bfr[2], bfr[3]);
            }
        }

        if (kt >= 2 * qtile) {
#pragma unroll
            for (int nt = 0; nt < 8; nt++)
#pragma unroll
                for (int i = 0; i < 4; i++) {
                    int rowg = qtile * FQ + w * 16 + g + (i >> 1) * 8;
                    int colg = kt * FK + nt * 8 + 2 * tig + (i & 1);
                    if (colg > rowg) sacc[nt][i] = -1e30f;
                }
        }

#pragma unroll
        for (int hh = 0; hh < 2; hh++) {
            float mx = -1e30f;
#pragma unroll
            for (int nt = 0; nt < 8; nt++)
                mx = fmaxf(mx, fmaxf(sacc[nt][2 * hh], sacc[nt][2 * hh + 1]));
            mx = fmaxf(mx, __shfl_xor_sync(0xffffffffu, mx, 1));
            mx = fmaxf(mx, __shfl_xor_sync(0xffffffffu, mx, 2));
            float mn = fmaxf(m[hh], mx);
            float fac = __expf(m[hh] - mn);
            m[hh] = mn;
            float rs = 0.f;
#pragma unroll
            for (int nt = 0; nt < 8; nt++) {
                float p0 = __expf(sacc[nt][2 * hh]     - mn);
                float p1 = __expf(sacc[nt][2 * hh + 1] - mn);
                sacc[nt][2 * hh] = p0; sacc[nt][2 * hh + 1] = p1;
                rs += p0 + p1;
            }
            rs += __shfl_xor_sync(0xffffffffu, rs, 1);
            rs += __shfl_xor_sync(0xffffffffu, rs, 2);
            l[hh] = l[hh] * fac + rs;
#pragma unroll
            for (int nt = 0; nt < 8; nt++) {
                oacc[nt][2 * hh]     *= fac;
                oacc[nt][2 * hh + 1] *= fac;
            }
        }

#pragma unroll
        for (int nt = 0; nt < 8; nt++) {
            uint2 p01, p23;
            p01.x = f2tf(sacc[nt][0]); p01.y = f2tf(sacc[nt][1]);
            p23.x = f2tf(sacc[nt][2]); p23.y = f2tf(sacc[nt][3]);
            *(uint2*)&Ps[(w * 16 + g)     * QP + nt * 8 + 2 * tig] = p01;
            *(uint2*)&Ps[(w * 16 + g + 8) * QP + nt * 8 + 2 * tig] = p23;
        }
        __syncwarp();

#pragma unroll
        for (int ks = 0; ks < 8; ks++) {
            uint32_t pf[4];
            ldm4(pf, &Ps[(w * 16 + qlRow) * QP + ks * 8 + qlCol]);
#pragma unroll
            for (int nt = 0; nt < 8; nt++) {
                uint32_t b0 = Vs[(ks * 8 + tig) * VP + nt * 8 + g];
                uint32_t b1 = Vs[(ks * 8 + tig + 4) * VP + nt * 8 + g];
                mma_tf32(oacc[nt], pf, b0, b1);
            }
        }
    }

    float inv0 = 1.0f / l[0], inv1 = 1.0f / l[1];
#pragma unroll
    for (int nt = 0; nt < 8; nt++) {
        size_t row0 = qtok0 + w * 16 + g;
        int col = h * HD + nt * 8 + 2 * tig;
        uint2 u0 = make_uint2(f2tf(oacc[nt][0] * inv0), f2tf(oacc[nt][1] * inv0));
        uint2 u1 = make_uint2(f2tf(oacc[nt][2] * inv1), f2tf(oacc[nt][3] * inv1));
        *(uint2*)&O[row0 * HDIM + col]       = u0;
        *(uint2*)&O[(row0 + 8) * HDIM + col] = u1;
    }
}

// ---------------- launch ----------------
extern "C" void kernel_launch(void* const* d_in, const int* in_sizes, int n_in,
                              void* d_out, int out_size) {
    const float* x  = (const float*)d_in[0];
    const float* wq = (const float*)d_in[1];
    const float* wk = (const float*)d_in[2];
    const float* wv = (const float*)d_in[3];
    const float* wo = (const float*)d_in[4];
    float* out = (float*)d_out;

    uint32_t *xb, *wqb, *wkb, *wvb, *wob, *q, *k, *v, *attn;
    float2* cs;
    cudaGetSymbolAddress((void**)&xb,   g_x);
    cudaGetSymbolAddress((void**)&wqb,  g_wq);
    cudaGetSymbolAddress((void**)&wkb,  g_wk);
    cudaGetSymbolAddress((void**)&wvb,  g_wv);
    cudaGetSymbolAddress((void**)&wob,  g_wo);
    cudaGetSymbolAddress((void**)&q,    g_q);
    cudaGetSymbolAddress((void**)&k,    g_k);
    cudaGetSymbolAddress((void**)&v,    g_v);
    cudaGetSymbolAddress((void**)&attn, g_attn);
    cudaGetSymbolAddress((void**)&cs,   g_cs);

    cudaFuncSetAttribute(gemm_qkv, cudaFuncAttributeMaxDynamicSharedMemorySize, GEMM_SMEM);
    cudaFuncSetAttribute(gemm_wo,  cudaFuncAttributeMaxDynamicSharedMemorySize, GEMM_SMEM);
    cudaFuncSetAttribute(flash_tc, cudaFuncAttributeMaxDynamicSharedMemorySize, FLASH_SMEM);

    cossin_kernel<<<(T_SEQ * 32) / 256, 256>>>(cs);

    {
        int n4 = NTOK * HDIM / 4;
        cvt_tf32_kernel<<<(n4 + 255) / 256, 256>>>((const float4*)x, (uint4*)xb, n4);
    }
    cvt_t_kernel<<<dim3(HDIM / 32, HDIM / 32),  256>>>(wq, wqb, HDIM,  HDIM);
    cvt_t_kernel<<<dim3(KVDIM / 32, HDIM / 32), 256>>>(wk, wkb, KVDIM, HDIM);
    cvt_t_kernel<<<dim3(KVDIM / 32, HDIM / 32), 256>>>(wv, wvb, KVDIM, HDIM);
    cvt_t_kernel<<<dim3(HDIM / 32, HDIM / 32),  256>>>(wo, wob, HDIM,  HDIM);

    gemm_qkv<<<dim3(24, NTOK / BM), 256, GEMM_SMEM>>>(xb, wqb, wkb, wvb, q, k, v, cs);

    flash_tc<<<dim3(T_SEQ / FQ, NH, 2), 256, FLASH_SMEM>>>(q, k, v, attn);

    gemm_wo<<<dim3(HDIM / BN, NTOK / BM), 256, GEMM_SMEM>>>(attn, wob, out);
}